// round 2
// baseline (speedup 1.0000x reference)
#include <cuda_runtime.h>
#include <cuda_bf16.h>

// 2x FIR upsample (upfirdn2d), separable [1,3,3,1]/4 tap, depthwise, fp32.
// Input (B*C, 128, 128) -> Output (B*C, 256, 256).
//
//   out[2y  ] = (1*x[y-1] + 3*x[y  ]) / 4   vertically, same horizontally
//   out[2y+1] = (3*x[y  ] + 1*x[y+1]) / 4
//
// Each thread computes a 4x8 output block (out rows 4t..4t+3, out cols 8*tx..8*tx+7)
// from input rows 2t-1..2t+2, input cols xb-1..xb+4 (xb = 4*tx).
// Horizontal filter results are shared across the two output rows of each parity pair.

#define H_IN  128
#define W_IN  128
#define W_OUT 256

__device__ __forceinline__ void stcs4(float* p, float4 v) {
    asm volatile("st.global.cs.v4.f32 [%0], {%1,%2,%3,%4};"
                 :: "l"(p), "f"(v.x), "f"(v.y), "f"(v.z), "f"(v.w) : "memory");
}

__global__ __launch_bounds__(256) void upfir2x_kernel(
    const float* __restrict__ in, float* __restrict__ out)
{
    const int plane = blockIdx.z;
    const int tx = threadIdx.x;                         // 0..31 -> 8 out cols each
    const int t  = blockIdx.y * blockDim.y + threadIdx.y;  // 0..63 -> out rows 4t..4t+3

    const float* src = in + (size_t)plane * (H_IN * W_IN);
    const int xb = tx * 4;                              // input col base (float4-aligned)
    const int row0 = 2 * t - 1;                         // input rows row0..row0+3

    // Load 4 input rows x 6 cols (zero-filled OOB), compute 8 horizontal taps each.
    float h[4][8];
    #pragma unroll
    for (int j = 0; j < 4; j++) {
        const int row = row0 + j;
        float p = 0.f, n = 0.f;
        float4 v = make_float4(0.f, 0.f, 0.f, 0.f);
        if (row >= 0 && row < H_IN) {
            const float* r = src + row * W_IN;
            if (xb > 0)          p = __ldg(r + xb - 1);
            v = *reinterpret_cast<const float4*>(r + xb);
            if (xb + 4 < W_IN)   n = __ldg(r + xb + 4);
        }
        // out col 2x   : 1*c[x-1] + 3*c[x]
        // out col 2x+1 : 3*c[x]   + 1*c[x+1]
        h[j][0] = fmaf(3.f, v.x, p);
        h[j][1] = fmaf(3.f, v.x, v.y);
        h[j][2] = fmaf(3.f, v.y, v.x);
        h[j][3] = fmaf(3.f, v.y, v.z);
        h[j][4] = fmaf(3.f, v.z, v.y);
        h[j][5] = fmaf(3.f, v.z, v.w);
        h[j][6] = fmaf(3.f, v.w, v.z);
        h[j][7] = fmaf(3.f, v.w, n);
    }

    // Vertical combine. Out rows:
    //   4t   = 1*h[0] + 3*h[1]
    //   4t+1 = 3*h[1] + 1*h[2]
    //   4t+2 = 1*h[1] + 3*h[2]
    //   4t+3 = 3*h[2] + 1*h[3]
    const float s = 1.0f / 16.0f;
    float* dst = out + (size_t)plane * (W_OUT * W_OUT) + (size_t)(4 * t) * W_OUT + tx * 8;

    #pragma unroll
    for (int i = 0; i < 4; i++) {
        const int jA = (i == 0) ? 0 : (i == 3 ? 2 : 1);
        const int jB = jA + 1;
        const float wA = (i == 1 || i == 3) ? 3.f : 1.f;
        const float wB = 4.f - wA;  // {1,3}->{3,1}

        float o[8];
        #pragma unroll
        for (int c = 0; c < 8; c++)
            o[c] = (wA * h[jA][c] + wB * h[jB][c]) * s;

        float* d = dst + (size_t)i * W_OUT;
        stcs4(d,     make_float4(o[0], o[1], o[2], o[3]));
        stcs4(d + 4, make_float4(o[4], o[5], o[6], o[7]));
    }
}

extern "C" void kernel_launch(void* const* d_in, const int* in_sizes, int n_in,
                              void* d_out, int out_size) {
    const float* x = (const float*)d_in[0];
    float* out = (float*)d_out;

    const int planes = in_sizes[0] / (H_IN * W_IN);   // B*C = 1024

    dim3 block(32, 8, 1);            // 256 threads: 32 cols x 8 row-groups
    dim3 grid(1, 64 / 8, planes);    // 8 row-group blocks x 1024 planes
    upfir2x_kernel<<<grid, block>>>(x, out);
}

// round 3
// speedup vs baseline: 1.2948x; 1.2948x over previous
#include <cuda_runtime.h>
#include <cuda_bf16.h>

// 2x FIR upsample (upfirdn2d), separable [1,3,3,1]/4 tap, depthwise, fp32.
// Input (B*C, 128, 128) -> Output (B*C, 256, 256).
//
//   out[2y  ] = (1*x[y-1] + 3*x[y  ]) / 4   vertically, same horizontally
//   out[2y+1] = (3*x[y  ] + 1*x[y+1]) / 4
//
// Thread layout: tx in [0,64) covers out cols 4*tx..4*tx+3 (input cols 2tx-1..2tx+2).
// Each thread computes 4 output rows (4t..4t+3) from input rows 2t-1..2t+2,
// reusing middle-row horizontal taps across output-row pairs.
// Warp stores are 512B contiguous (perfectly coalesced float4).

#define H_IN  128
#define W_IN  128
#define W_OUT 256

__device__ __forceinline__ void stcs4(float* p, float4 v) {
    asm volatile("st.global.cs.v4.f32 [%0], {%1,%2,%3,%4};"
                 :: "l"(p), "f"(v.x), "f"(v.y), "f"(v.z), "f"(v.w) : "memory");
}

__global__ __launch_bounds__(256) void upfir2x_kernel(
    const float* __restrict__ in, float* __restrict__ out)
{
    const int plane = blockIdx.z;
    const int tx = threadIdx.x;                            // 0..63 -> out cols 4tx..4tx+3
    const int t  = blockIdx.y * blockDim.y + threadIdx.y;  // 0..63 -> out rows 4t..4t+3

    const float* src = in + (size_t)plane * (H_IN * W_IN);
    const int xc = 2 * tx;          // input col base; need cols xc-1 .. xc+2
    const int row0 = 2 * t - 1;     // input rows row0 .. row0+3

    // Per input row: 4 horizontal taps (unnormalized) for out cols 4tx..4tx+3.
    float h[4][4];
    #pragma unroll
    for (int j = 0; j < 4; j++) {
        const int row = row0 + j;
        float p = 0.f, n = 0.f;
        float2 v = make_float2(0.f, 0.f);
        if (row >= 0 && row < H_IN) {
            const float* r = src + row * W_IN;
            if (xc > 0)         p = __ldg(r + xc - 1);
            v = *reinterpret_cast<const float2*>(r + xc);   // 8B-aligned
            if (xc + 2 < W_IN)  n = __ldg(r + xc + 2);
        }
        h[j][0] = fmaf(3.f, v.x, p);     // out col 4tx   : in[2tx-1] + 3*in[2tx]
        h[j][1] = fmaf(3.f, v.x, v.y);   // out col 4tx+1 : 3*in[2tx] + in[2tx+1]
        h[j][2] = fmaf(3.f, v.y, v.x);   // out col 4tx+2 : in[2tx] + 3*in[2tx+1]
        h[j][3] = fmaf(3.f, v.y, n);     // out col 4tx+3 : 3*in[2tx+1] + in[2tx+2]
    }

    // Vertical combine (unnormalized weights, /16 at the end):
    //   out row 4t   = 1*h[0] + 3*h[1]
    //   out row 4t+1 = 3*h[1] + 1*h[2]
    //   out row 4t+2 = 1*h[1] + 3*h[2]
    //   out row 4t+3 = 3*h[2] + 1*h[3]
    const float s = 1.0f / 16.0f;
    float* dst = out + (size_t)plane * (W_OUT * W_OUT)
                     + (size_t)(4 * t) * W_OUT + tx * 4;

    {
        float4 o;
        o.x = fmaf(3.f, h[1][0], h[0][0]) * s;
        o.y = fmaf(3.f, h[1][1], h[0][1]) * s;
        o.z = fmaf(3.f, h[1][2], h[0][2]) * s;
        o.w = fmaf(3.f, h[1][3], h[0][3]) * s;
        stcs4(dst, o);
    }
    {
        float4 o;
        o.x = fmaf(3.f, h[1][0], h[2][0]) * s;
        o.y = fmaf(3.f, h[1][1], h[2][1]) * s;
        o.z = fmaf(3.f, h[1][2], h[2][2]) * s;
        o.w = fmaf(3.f, h[1][3], h[2][3]) * s;
        stcs4(dst + W_OUT, o);
    }
    {
        float4 o;
        o.x = fmaf(3.f, h[2][0], h[1][0]) * s;
        o.y = fmaf(3.f, h[2][1], h[1][1]) * s;
        o.z = fmaf(3.f, h[2][2], h[1][2]) * s;
        o.w = fmaf(3.f, h[2][3], h[1][3]) * s;
        stcs4(dst + 2 * W_OUT, o);
    }
    {
        float4 o;
        o.x = fmaf(3.f, h[2][0], h[3][0]) * s;
        o.y = fmaf(3.f, h[2][1], h[3][1]) * s;
        o.z = fmaf(3.f, h[2][2], h[3][2]) * s;
        o.w = fmaf(3.f, h[2][3], h[3][3]) * s;
        stcs4(dst + 3 * W_OUT, o);
    }
}

extern "C" void kernel_launch(void* const* d_in, const int* in_sizes, int n_in,
                              void* d_out, int out_size) {
    const float* x = (const float*)d_in[0];
    float* out = (float*)d_out;

    const int planes = in_sizes[0] / (H_IN * W_IN);   // B*C = 1024

    dim3 block(64, 4, 1);            // 256 threads: 64 col-quads x 4 row-groups
    dim3 grid(1, 64 / 4, planes);    // 16 row-group blocks x 1024 planes
    upfir2x_kernel<<<grid, block>>>(x, out);
}

// round 4
// speedup vs baseline: 1.3405x; 1.0353x over previous
#include <cuda_runtime.h>
#include <cuda_bf16.h>

// 2x FIR upsample (upfirdn2d), separable [1,3,3,1]/4 tap, depthwise, fp32.
// Input (B*C, 128, 128) -> Output (B*C, 256, 256).
//
//   out[2y  ] = (1*x[y-1] + 3*x[y  ]) / 4   vertically, same horizontally
//   out[2y+1] = (3*x[y  ] + 1*x[y+1]) / 4
//
// Thread tx in [0,64) covers out cols 4tx..4tx+3 (input cols 2tx-1..2tx+2).
// Each thread computes 4 output rows (4t..4t+3) from input rows 2t-1..2t+2.
// Halo input values come from neighbor lanes via warp shuffle; only warp-edge
// lanes issue predicated scalar loads. Warp stores are 512B contiguous.

#define H_IN  128
#define W_IN  128
#define W_OUT 256

__device__ __forceinline__ void stcs4(float* p, float4 v) {
    asm volatile("st.global.cs.v4.f32 [%0], {%1,%2,%3,%4};"
                 :: "l"(p), "f"(v.x), "f"(v.y), "f"(v.z), "f"(v.w) : "memory");
}

__global__ __launch_bounds__(256) void upfir2x_kernel(
    const float* __restrict__ in, float* __restrict__ out)
{
    const int plane = blockIdx.z;
    const int tx = threadIdx.x;                            // 0..63 -> out cols 4tx..4tx+3
    const int t  = blockIdx.y * blockDim.y + threadIdx.y;  // 0..63 -> out rows 4t..4t+3
    const int lane = tx & 31;                              // warps are contiguous in tx

    const float* src = in + (size_t)plane * (H_IN * W_IN);
    const int xc = 2 * tx;          // input col base; need cols xc-1 .. xc+2
    const int row0 = 2 * t - 1;     // input rows row0 .. row0+3

    // Per input row: 4 horizontal taps (unnormalized) for out cols 4tx..4tx+3.
    float h[4][4];
    #pragma unroll
    for (int j = 0; j < 4; j++) {
        const int row = row0 + j;
        float2 v = make_float2(0.f, 0.f);
        float pe = 0.f, ne = 0.f;       // edge-lane halo values
        if (row >= 0 && row < H_IN) {   // uniform across the warp
            const float* r = src + row * W_IN;
            v = *reinterpret_cast<const float2*>(r + xc);   // 8B-aligned, coalesced
            if (lane == 0  && xc > 0)        pe = __ldg(r + xc - 1);
            if (lane == 31 && xc + 2 < W_IN) ne = __ldg(r + xc + 2);
        }
        // halo via shuffle: p = lane-1's v.y, n = lane+1's v.x
        float p = __shfl_up_sync(0xffffffffu, v.y, 1);
        float n = __shfl_down_sync(0xffffffffu, v.x, 1);
        if (lane == 0)  p = pe;
        if (lane == 31) n = ne;

        h[j][0] = fmaf(3.f, v.x, p);     // out col 4tx   : in[2tx-1] + 3*in[2tx]
        h[j][1] = fmaf(3.f, v.x, v.y);   // out col 4tx+1 : 3*in[2tx] + in[2tx+1]
        h[j][2] = fmaf(3.f, v.y, v.x);   // out col 4tx+2 : in[2tx] + 3*in[2tx+1]
        h[j][3] = fmaf(3.f, v.y, n);     // out col 4tx+3 : 3*in[2tx+1] + in[2tx+2]
    }

    // Vertical combine (unnormalized, /16 at end):
    //   4t   = 1*h[0] + 3*h[1]
    //   4t+1 = 3*h[1] + 1*h[2]
    //   4t+2 = 1*h[1] + 3*h[2]
    //   4t+3 = 3*h[2] + 1*h[3]
    const float s = 1.0f / 16.0f;
    float* dst = out + (size_t)plane * (W_OUT * W_OUT)
                     + (size_t)(4 * t) * W_OUT + tx * 4;

    {
        float4 o;
        o.x = fmaf(3.f, h[1][0], h[0][0]) * s;
        o.y = fmaf(3.f, h[1][1], h[0][1]) * s;
        o.z = fmaf(3.f, h[1][2], h[0][2]) * s;
        o.w = fmaf(3.f, h[1][3], h[0][3]) * s;
        stcs4(dst, o);
    }
    {
        float4 o;
        o.x = fmaf(3.f, h[1][0], h[2][0]) * s;
        o.y = fmaf(3.f, h[1][1], h[2][1]) * s;
        o.z = fmaf(3.f, h[1][2], h[2][2]) * s;
        o.w = fmaf(3.f, h[1][3], h[2][3]) * s;
        stcs4(dst + W_OUT, o);
    }
    {
        float4 o;
        o.x = fmaf(3.f, h[2][0], h[1][0]) * s;
        o.y = fmaf(3.f, h[2][1], h[1][1]) * s;
        o.z = fmaf(3.f, h[2][2], h[1][2]) * s;
        o.w = fmaf(3.f, h[2][3], h[1][3]) * s;
        stcs4(dst + 2 * W_OUT, o);
    }
    {
        float4 o;
        o.x = fmaf(3.f, h[2][0], h[3][0]) * s;
        o.y = fmaf(3.f, h[2][1], h[3][1]) * s;
        o.z = fmaf(3.f, h[2][2], h[3][2]) * s;
        o.w = fmaf(3.f, h[2][3], h[3][3]) * s;
        stcs4(dst + 3 * W_OUT, o);
    }
}

extern "C" void kernel_launch(void* const* d_in, const int* in_sizes, int n_in,
                              void* d_out, int out_size) {
    const float* x = (const float*)d_in[0];
    float* out = (float*)d_out;

    const int planes = in_sizes[0] / (H_IN * W_IN);   // B*C = 1024

    dim3 block(64, 4, 1);            // 256 threads: 64 col-quads x 4 row-groups
    dim3 grid(1, 64 / 4, planes);    // 16 row-group blocks x 1024 planes
    upfir2x_kernel<<<grid, block>>>(x, out);
}